// round 2
// baseline (speedup 1.0000x reference)
#include <cuda_runtime.h>
#include <cuda_bf16.h>

// Problem constants
#define BB   16
#define NN   2048
#define SS   2048
#define DD   256

// ---------------------------------------------------------------------------
// GEMM 1: scores[b,i,j] = sum_d Q[b,i,d] * K[b,j,d]   (NT GEMM, fp32)
// Tile: BM=BN=128, BK=16, 256 threads, 8x8 micro-tile per thread (4+4 split)
// ---------------------------------------------------------------------------
__global__ __launch_bounds__(256) void qk_kernel(
    const float* __restrict__ Q, const float* __restrict__ K,
    float* __restrict__ C)
{
    __shared__ float Qs[16][128];
    __shared__ float Ks[16][128];

    const int b = blockIdx.z;
    const float* Qb = Q + (size_t)b * NN * DD;
    const float* Kb = K + (size_t)b * NN * DD;
    float* Cb = C + (size_t)b * NN * SS;

    const int rowBase = blockIdx.y * 128;
    const int colBase = blockIdx.x * 128;
    const int tid = threadIdx.x;
    const int rx = tid & 15;      // 0..15 -> cols
    const int ry = tid >> 4;      // 0..15 -> rows

    float acc[8][8];
#pragma unroll
    for (int i = 0; i < 8; ++i)
#pragma unroll
        for (int j = 0; j < 8; ++j) acc[i][j] = 0.0f;

    for (int k0 = 0; k0 < DD; k0 += 16) {
        // Load 128x16 tiles of Q and K, store transposed into smem.
#pragma unroll
        for (int l = 0; l < 2; ++l) {
            int f   = tid + l * 256;      // 0..511
            int row = f >> 2;             // 0..127
            int c4  = (f & 3) * 4;        // 0,4,8,12
            float4 q = *(const float4*)&Qb[(size_t)(rowBase + row) * DD + k0 + c4];
            Qs[c4 + 0][row] = q.x; Qs[c4 + 1][row] = q.y;
            Qs[c4 + 2][row] = q.z; Qs[c4 + 3][row] = q.w;
            float4 kk = *(const float4*)&Kb[(size_t)(colBase + row) * DD + k0 + c4];
            Ks[c4 + 0][row] = kk.x; Ks[c4 + 1][row] = kk.y;
            Ks[c4 + 2][row] = kk.z; Ks[c4 + 3][row] = kk.w;
        }
        __syncthreads();

#pragma unroll
        for (int k = 0; k < 16; ++k) {
            float4 a0 = *(const float4*)&Qs[k][ry * 4];
            float4 a1 = *(const float4*)&Qs[k][64 + ry * 4];
            float4 b0 = *(const float4*)&Ks[k][rx * 4];
            float4 b1 = *(const float4*)&Ks[k][64 + rx * 4];
            float av[8] = {a0.x, a0.y, a0.z, a0.w, a1.x, a1.y, a1.z, a1.w};
            float bv[8] = {b0.x, b0.y, b0.z, b0.w, b1.x, b1.y, b1.z, b1.w};
#pragma unroll
            for (int i = 0; i < 8; ++i)
#pragma unroll
                for (int j = 0; j < 8; ++j)
                    acc[i][j] = fmaf(av[i], bv[j], acc[i][j]);
        }
        __syncthreads();
    }

#pragma unroll
    for (int i = 0; i < 8; ++i) {
        int r = rowBase + ((i < 4) ? (ry * 4 + i) : (64 + ry * 4 + i - 4));
        float4 v0 = make_float4(acc[i][0], acc[i][1], acc[i][2], acc[i][3]);
        float4 v1 = make_float4(acc[i][4], acc[i][5], acc[i][6], acc[i][7]);
        *(float4*)&Cb[(size_t)r * SS + colBase + rx * 4]      = v0;
        *(float4*)&Cb[(size_t)r * SS + colBase + 64 + rx * 4] = v1;
    }
}

// ---------------------------------------------------------------------------
// Sparsemax: one CTA per row (B*N rows of S=2048).
// tau is the root of f(t) = sum relu(z_i - t) - 1 on [zmax-1, zmax]:
// bisection then exact recompute tau = (sum_{z>lo} z - 1) / count.
// Reads scores from G (scratch = gates region), writes gates to G and A.
// ---------------------------------------------------------------------------
__global__ __launch_bounds__(256) void sparsemax_kernel(
    float* __restrict__ G, float* __restrict__ A)
{
    __shared__ float red[8];
    __shared__ float red2[8];

    const size_t row = blockIdx.x;
    float* z  = G + row * SS;
    float* ao = A + row * SS;
    const int tid  = threadIdx.x;
    const int lane = tid & 31;
    const int wrp  = tid >> 5;

    float v[8];
#pragma unroll
    for (int e = 0; e < 8; ++e) v[e] = z[tid + e * 256];

    // --- block max ---
    float m = v[0];
#pragma unroll
    for (int e = 1; e < 8; ++e) m = fmaxf(m, v[e]);
#pragma unroll
    for (int o = 16; o > 0; o >>= 1) m = fmaxf(m, __shfl_xor_sync(0xffffffffu, m, o));
    if (lane == 0) red[wrp] = m;
    __syncthreads();
    float zmax = red[0];
#pragma unroll
    for (int w = 1; w < 8; ++w) zmax = fmaxf(zmax, red[w]);
    __syncthreads();

    // --- bisection for tau ---
    float lo = zmax - 1.0f;
    float hi = zmax;
    for (int it = 0; it < 28; ++it) {
        float mid = 0.5f * (lo + hi);
        float s = 0.0f;
#pragma unroll
        for (int e = 0; e < 8; ++e) s += fmaxf(v[e] - mid, 0.0f);
#pragma unroll
        for (int o = 16; o > 0; o >>= 1) s += __shfl_xor_sync(0xffffffffu, s, o);
        if (lane == 0) red[wrp] = s;
        __syncthreads();
        float st = red[0];
#pragma unroll
        for (int w = 1; w < 8; ++w) st += red[w];   // identical in all threads
        if (st >= 1.0f) lo = mid; else hi = mid;
        __syncthreads();
    }

    // --- exact tau from support set {z > lo} ---
    float cnt = 0.0f, sm = 0.0f;
#pragma unroll
    for (int e = 0; e < 8; ++e) {
        if (v[e] > lo) { cnt += 1.0f; sm += v[e]; }
    }
#pragma unroll
    for (int o = 16; o > 0; o >>= 1) {
        cnt += __shfl_xor_sync(0xffffffffu, cnt, o);
        sm  += __shfl_xor_sync(0xffffffffu, sm, o);
    }
    if (lane == 0) { red[wrp] = cnt; red2[wrp] = sm; }
    __syncthreads();
    float ck = red[0], sk = red2[0];
#pragma unroll
    for (int w = 1; w < 8; ++w) { ck += red[w]; sk += red2[w]; }
    float tau = (sk - 1.0f) / ck;

    // --- write gates to both outputs (in-place into G, copy into A) ---
#pragma unroll
    for (int e = 0; e < 8; ++e) {
        float g = fmaxf(v[e] - tau, 0.0f);
        z[tid + e * 256]  = g;
        ao[tid + e * 256] = g;
    }
}

// ---------------------------------------------------------------------------
// GEMM 2: V[b,n,d] = sum_s A[b,n,s] * Vals[b,s,d]   (NN GEMM, fp32)
// ---------------------------------------------------------------------------
__global__ __launch_bounds__(256) void av_kernel(
    const float* __restrict__ A, const float* __restrict__ Vv,
    float* __restrict__ O)
{
    __shared__ float As[16][128];
    __shared__ float Bs[16][128];

    const int b = blockIdx.z;
    const float* Ab = A  + (size_t)b * NN * SS;
    const float* Vb = Vv + (size_t)b * SS * DD;
    float* Ob = O + (size_t)b * NN * DD;

    const int rowBase = blockIdx.y * 128;   // n
    const int colBase = blockIdx.x * 128;   // d
    const int tid = threadIdx.x;
    const int rx = tid & 15;
    const int ry = tid >> 4;

    float acc[8][8];
#pragma unroll
    for (int i = 0; i < 8; ++i)
#pragma unroll
        for (int j = 0; j < 8; ++j) acc[i][j] = 0.0f;

    for (int k0 = 0; k0 < SS; k0 += 16) {
#pragma unroll
        for (int l = 0; l < 2; ++l) {
            int f = tid + l * 256;          // 0..511
            // A tile [128 rows x 16 k], transposed store
            {
                int row = f >> 2;
                int c4  = (f & 3) * 4;
                float4 a = *(const float4*)&Ab[(size_t)(rowBase + row) * SS + k0 + c4];
                As[c4 + 0][row] = a.x; As[c4 + 1][row] = a.y;
                As[c4 + 2][row] = a.z; As[c4 + 3][row] = a.w;
            }
            // V tile [16 k x 128 cols], direct store
            {
                int krow = f >> 5;            // 0..15
                int cc   = (f & 31) * 4;      // 0..124
                float4 vv = *(const float4*)&Vb[(size_t)(k0 + krow) * DD + colBase + cc];
                *(float4*)&Bs[krow][cc] = vv;
            }
        }
        __syncthreads();

#pragma unroll
        for (int k = 0; k < 16; ++k) {
            float4 a0 = *(const float4*)&As[k][ry * 4];
            float4 a1 = *(const float4*)&As[k][64 + ry * 4];
            float4 b0 = *(const float4*)&Bs[k][rx * 4];
            float4 b1 = *(const float4*)&Bs[k][64 + rx * 4];
            float av[8] = {a0.x, a0.y, a0.z, a0.w, a1.x, a1.y, a1.z, a1.w};
            float bv[8] = {b0.x, b0.y, b0.z, b0.w, b1.x, b1.y, b1.z, b1.w};
#pragma unroll
            for (int i = 0; i < 8; ++i)
#pragma unroll
                for (int j = 0; j < 8; ++j)
                    acc[i][j] = fmaf(av[i], bv[j], acc[i][j]);
        }
        __syncthreads();
    }

#pragma unroll
    for (int i = 0; i < 8; ++i) {
        int r = rowBase + ((i < 4) ? (ry * 4 + i) : (64 + ry * 4 + i - 4));
        float4 v0 = make_float4(acc[i][0], acc[i][1], acc[i][2], acc[i][3]);
        float4 v1 = make_float4(acc[i][4], acc[i][5], acc[i][6], acc[i][7]);
        *(float4*)&Ob[(size_t)r * DD + colBase + rx * 4]      = v0;
        *(float4*)&Ob[(size_t)r * DD + colBase + 64 + rx * 4] = v1;
    }
}

// ---------------------------------------------------------------------------
// Launch: out layout is (V, A, gates) flattened in order.
// The gates region doubles as the scores scratch buffer.
// ---------------------------------------------------------------------------
extern "C" void kernel_launch(void* const* d_in, const int* in_sizes, int n_in,
                              void* d_out, int out_size)
{
    const float* Q  = (const float*)d_in[0];
    const float* K  = (const float*)d_in[1];
    const float* Vv = (const float*)d_in[2];

    float* out  = (float*)d_out;
    float* Vout = out;
    float* Aout = out + (size_t)BB * NN * DD;                 // 8,388,608
    float* Gout = Aout + (size_t)BB * NN * SS;                // +67,108,864

    // 1) scores = Q K^T  -> gates region (scratch)
    dim3 g1(SS / 128, NN / 128, BB);
    qk_kernel<<<g1, 256>>>(Q, K, Gout);

    // 2) sparsemax in place; write gates to both A and gates regions
    sparsemax_kernel<<<BB * NN, 256>>>(Gout, Aout);

    // 3) V = A @ values
    dim3 g2(DD / 128, NN / 128, BB);
    av_kernel<<<g2, 256>>>(Aout, Vv, Vout);
}

// round 5
// speedup vs baseline: 3.8389x; 3.8389x over previous
#include <cuda_runtime.h>
#include <cuda_fp16.h>
#include <cstdint>

#define BB 16
#define NN 2048
#define SS 2048
#define DD 256

#define KTOT 768      // fp16-split GEMM depth: [hi|lo|hi] x [hi|hi|lo]
#define BM 128
#define BN 128
#define BKH 64        // K-chunk in halves
#define LDSH 72       // smem row stride in halves (+8 pad)

__device__ __forceinline__ uint32_t smem_u32(const void* p) {
    uint32_t a;
    asm("{ .reg .u64 t; cvta.to.shared.u64 t, %1; cvt.u32.u64 %0, t; }"
        : "=r"(a) : "l"(p));
    return a;
}

__device__ __forceinline__ void cp16(uint32_t dst, const void* src) {
    asm volatile("cp.async.cg.shared.global [%0], [%1], 16;" :: "r"(dst), "l"(src));
}

// ---------------------------------------------------------------------------
// Pre-convert: Q'' = [Qh | Ql | Qh], K'' = [Kh | Kh | Kl]  (fp16, K=768)
// so that Q''.K''^T = qh.kh + ql.kh + qh.kl  ~= fp32 product (err ~1e-6 rel)
// ---------------------------------------------------------------------------
__global__ __launch_bounds__(256) void convert_kernel(
    const float* __restrict__ Q, const float* __restrict__ K,
    __half* __restrict__ Qc, __half* __restrict__ Kc)
{
    const size_t v = (size_t)blockIdx.x * 256 + threadIdx.x; // < BB*NN*DD/4
    const size_t row = v >> 6;            // 64 float4 per row of 256
    const int d = (int)(v & 63) * 4;

    float4 q = *(const float4*)(Q + row * DD + d);
    float4 k = *(const float4*)(K + row * DD + d);
    float qa[4] = {q.x, q.y, q.z, q.w};
    float ka[4] = {k.x, k.y, k.z, k.w};

    __half qh[4], ql[4], kh[4], kl[4];
#pragma unroll
    for (int e = 0; e < 4; ++e) {
        qh[e] = __float2half_rn(qa[e]);
        ql[e] = __float2half_rn(qa[e] - __half2float(qh[e]));
        kh[e] = __float2half_rn(ka[e]);
        kl[e] = __float2half_rn(ka[e] - __half2float(kh[e]));
    }
    uint2 qhp = *(uint2*)qh, qlp = *(uint2*)ql;
    uint2 khp = *(uint2*)kh, klp = *(uint2*)kl;

    __half* qd = Qc + row * KTOT + d;
    *(uint2*)(qd)       = qhp;
    *(uint2*)(qd + 256) = qlp;
    *(uint2*)(qd + 512) = qhp;

    __half* kd = Kc + row * KTOT + d;
    *(uint2*)(kd)       = khp;
    *(uint2*)(kd + 256) = khp;
    *(uint2*)(kd + 512) = klp;
}

// ---------------------------------------------------------------------------
// QK GEMM via HMMA mma.sync m16n8k16 (fp16 in, fp32 acc).
// CTA tile 128x128, 8 warps of 64x32, BK=64 halves, 2-stage cp.async.
// B is K-major in smem => NON-trans ldmatrix yields the correct B fragment.
// ---------------------------------------------------------------------------
__global__ __launch_bounds__(256) void qk_hmma(
    const __half* __restrict__ Qc, const __half* __restrict__ Kc,
    float* __restrict__ C)
{
    extern __shared__ __align__(16) char smraw[];
    __half* As = (__half*)smraw;          // [2][BM][LDSH]
    __half* Bs = As + 2 * BM * LDSH;      // [2][BN][LDSH]

    const int tid = threadIdx.x, wid = tid >> 5, lane = tid & 31;
    const int warp_m = wid & 1;           // 0..1 -> 64-row half
    const int warp_n = wid >> 1;          // 0..3 -> 32-col quarter
    const int b = blockIdx.z;
    const int rowBase = blockIdx.y * BM;
    const int colBase = blockIdx.x * BN;
    const __half* Qb = Qc + ((size_t)b * NN + rowBase) * KTOT;
    const __half* Kb = Kc + ((size_t)b * SS + colBase) * KTOT;
    const uint32_t asb = smem_u32(As);
    const uint32_t bsb = smem_u32(Bs);

    float acc[4][4][4];
#pragma unroll
    for (int mt = 0; mt < 4; ++mt)
#pragma unroll
        for (int nt = 0; nt < 4; ++nt)
#pragma unroll
            for (int e = 0; e < 4; ++e) acc[mt][nt][e] = 0.0f;

    // async-load one K-chunk (stage st): A and B tiles, 128 rows x 64 halves
#define ISSUE_STAGE(st, k0) do {                                              \
        _Pragma("unroll")                                                     \
        for (int l = 0; l < 4; ++l) {                                         \
            int idx = tid + l * 256;                                          \
            int row = idx >> 3;                                               \
            int c8  = (idx & 7) * 8;                                          \
            cp16(asb + (uint32_t)(((st) * BM * LDSH + row * LDSH + c8) * 2),  \
                 Qb + (size_t)row * KTOT + (k0) + c8);                        \
            cp16(bsb + (uint32_t)(((st) * BN * LDSH + row * LDSH + c8) * 2),  \
                 Kb + (size_t)row * KTOT + (k0) + c8);                        \
        }                                                                     \
        asm volatile("cp.async.commit_group;" ::: "memory");                  \
    } while (0)

    ISSUE_STAGE(0, 0);
    const int NK = KTOT / BKH;   // 12

    for (int c = 0; c < NK; ++c) {
        if (c + 1 < NK) {
            ISSUE_STAGE((c + 1) & 1, (c + 1) * BKH);
            asm volatile("cp.async.wait_group 1;" ::: "memory");
        } else {
            asm volatile("cp.async.wait_group 0;" ::: "memory");
        }
        __syncthreads();

        const int st = c & 1;
        const uint32_t ab = asb + (uint32_t)(st * BM * LDSH * 2);
        const uint32_t bbs = bsb + (uint32_t)(st * BN * LDSH * 2);

#pragma unroll
        for (int ks = 0; ks < BKH / 16; ++ks) {
            uint32_t a[4][4];
#pragma unroll
            for (int mt = 0; mt < 4; ++mt) {
                uint32_t addr = ab + (uint32_t)((((warp_m * 64 + mt * 16 + (lane & 15)) * LDSH)
                                 + ks * 16 + (lane >> 4) * 8) * 2);
                asm volatile(
                    "ldmatrix.sync.aligned.m8n8.x4.shared.b16 {%0,%1,%2,%3}, [%4];"
                    : "=r"(a[mt][0]), "=r"(a[mt][1]), "=r"(a[mt][2]), "=r"(a[mt][3])
                    : "r"(addr));
            }
            // B fragments: K-major smem rows are n-indices -> NON-trans ldmatrix.
            // matrix0: n g*16+0..7,  k 0..8   -> b0 of nt=g*2
            // matrix1: n g*16+8..15, k 0..8   -> b0 of nt=g*2+1
            // matrix2: n g*16+0..7,  k 8..16  -> b1 of nt=g*2
            // matrix3: n g*16+8..15, k 8..16  -> b1 of nt=g*2+1
            uint32_t bf[4][2];
#pragma unroll
            for (int g = 0; g < 2; ++g) {
                uint32_t addr = bbs + (uint32_t)((((warp_n * 32 + g * 16 + (lane & 15)) * LDSH)
                                 + ks * 16 + (lane >> 4) * 8) * 2);
                uint32_t r0, r1, r2, r3;
                asm volatile(
                    "ldmatrix.sync.aligned.m8n8.x4.shared.b16 {%0,%1,%2,%3}, [%4];"
                    : "=r"(r0), "=r"(r1), "=r"(r2), "=r"(r3)
                    : "r"(addr));
                bf[g * 2][0] = r0; bf[g * 2][1] = r2;
                bf[g * 2 + 1][0] = r1; bf[g * 2 + 1][1] = r3;
            }
#pragma unroll
            for (int mt = 0; mt < 4; ++mt)
#pragma unroll
                for (int nt = 0; nt < 4; ++nt) {
                    asm volatile(
                        "mma.sync.aligned.m16n8k16.row.col.f32.f16.f16.f32 "
                        "{%0,%1,%2,%3}, {%4,%5,%6,%7}, {%8,%9}, {%0,%1,%2,%3};"
                        : "+f"(acc[mt][nt][0]), "+f"(acc[mt][nt][1]),
                          "+f"(acc[mt][nt][2]), "+f"(acc[mt][nt][3])
                        : "r"(a[mt][0]), "r"(a[mt][1]), "r"(a[mt][2]), "r"(a[mt][3]),
                          "r"(bf[nt][0]), "r"(bf[nt][1]));
                }
        }
        __syncthreads();
    }

    // Epilogue: fp32 scores
    float* Cb = C + (size_t)b * NN * SS;
#pragma unroll
    for (int mt = 0; mt < 4; ++mt) {
        int r0 = rowBase + warp_m * 64 + mt * 16 + (lane >> 2);
#pragma unroll
        for (int nt = 0; nt < 4; ++nt) {
            int cc = colBase + warp_n * 32 + nt * 8 + (lane & 3) * 2;
            *(float2*)&Cb[(size_t)r0 * SS + cc] =
                make_float2(acc[mt][nt][0], acc[mt][nt][1]);
            *(float2*)&Cb[(size_t)(r0 + 8) * SS + cc] =
                make_float2(acc[mt][nt][2], acc[mt][nt][3]);
        }
    }
#undef ISSUE_STAGE
}

// ================= Fused sparsemax + AV-gather + gate writes ===============
// One warp per row. Candidates (z > zmax-1) are the only possible support.
__global__ void __launch_bounds__(256) sparse_fused(
    float* __restrict__ G, float* __restrict__ A,
    float* __restrict__ Vout, const float* __restrict__ Vals)
{
    __shared__ float cv[8][32];
    __shared__ int   ci[8][32];

    const int tid = threadIdx.x, wid = tid >> 5, lane = tid & 31;
    const int row = blockIdx.x * 8 + wid;       // 0..32767
    const int b = row >> 11;
    float* z = G + (size_t)row * SS;
    float* a = A + (size_t)row * SS;

    // Load full row (64 floats / lane, coalesced float4)
    float4 v4[16];
#pragma unroll
    for (int j = 0; j < 16; ++j) v4[j] = *(const float4*)&z[(j * 32 + lane) * 4];

    // Row max
    float m = -1e30f;
#pragma unroll
    for (int j = 0; j < 16; ++j) {
        m = fmaxf(m, fmaxf(fmaxf(v4[j].x, v4[j].y), fmaxf(v4[j].z, v4[j].w)));
    }
#pragma unroll
    for (int o = 16; o > 0; o >>= 1) m = fmaxf(m, __shfl_xor_sync(0xffffffffu, m, o));

    // Candidate extraction: z > zmax - 1 (support superset, typically 1-3 elems)
    const float thr = m - 1.0f;
    int base = 0;
#pragma unroll
    for (int j = 0; j < 16; ++j) {
        const float* vv = (const float*)&v4[j];
#pragma unroll
        for (int e = 0; e < 4; ++e) {
            float val = vv[e];
            unsigned msk = __ballot_sync(0xffffffffu, val > thr);
            if (val > thr) {
                int pos = base + __popc(msk & ((1u << lane) - 1u));
                if (pos < 32) { cv[wid][pos] = val; ci[wid][pos] = (j * 32 + lane) * 4 + e; }
            }
            base += __popc(msk);
        }
    }
    const int mc = base > 32 ? 32 : base;
    __syncwarp();

    // Bisection for tau on candidates only (tau in [zmax-1, zmax])
    float cand = (lane < mc) ? cv[wid][lane] : -1e30f;
    float lo = thr, hi = m;
    for (int it = 0; it < 20; ++it) {
        float mid = 0.5f * (lo + hi);
        float s = fmaxf(cand - mid, 0.0f);
#pragma unroll
        for (int o = 16; o > 0; o >>= 1) s += __shfl_xor_sync(0xffffffffu, s, o);
        if (s >= 1.0f) lo = mid; else hi = mid;   // uniform across warp
    }
    // Exact tau from identified support {cand > lo}
    float inz = (cand > lo) ? cand : 0.0f;
    float inc = (cand > lo) ? 1.0f : 0.0f;
#pragma unroll
    for (int o = 16; o > 0; o >>= 1) {
        inz += __shfl_xor_sync(0xffffffffu, inz, o);
        inc += __shfl_xor_sync(0xffffffffu, inc, o);
    }
    const float tau = (inz - 1.0f) / inc;
    const float g = fmaxf(cand - tau, 0.0f);      // per-lane gate for its candidate

    // V[row,:] = sum_i g_i * Vals[b, s_i, :]  (gather; 8 floats per lane)
    float4 acc0 = make_float4(0.f, 0.f, 0.f, 0.f);
    float4 acc1 = make_float4(0.f, 0.f, 0.f, 0.f);
    for (int i = 0; i < mc; ++i) {
        float gi = __shfl_sync(0xffffffffu, g, i);
        if (gi > 0.0f) {
            const float4* vr = (const float4*)(Vals + ((size_t)b * SS + ci[wid][i]) * DD + lane * 8);
            float4 p0 = vr[0], p1 = vr[1];
            acc0.x += gi * p0.x; acc0.y += gi * p0.y; acc0.z += gi * p0.z; acc0.w += gi * p0.w;
            acc1.x += gi * p1.x; acc1.y += gi * p1.y; acc1.z += gi * p1.z; acc1.w += gi * p1.w;
        }
    }
    float4* vo = (float4*)(Vout + (size_t)row * DD + lane * 8);
    vo[0] = acc0; vo[1] = acc1;

    // Gates: zero-fill both outputs, then scatter the few nonzeros.
    const float4 z4 = make_float4(0.f, 0.f, 0.f, 0.f);
#pragma unroll
    for (int j = 0; j < 16; ++j) {
        *(float4*)&z[(j * 32 + lane) * 4] = z4;
        *(float4*)&a[(j * 32 + lane) * 4] = z4;
    }
    __syncwarp();
    if (lane < mc && g > 0.0f) {
        int s = ci[wid][lane];
        z[s] = g;
        a[s] = g;
    }
}

// ============================== launch =====================================
extern "C" void kernel_launch(void* const* d_in, const int* in_sizes, int n_in,
                              void* d_out, int out_size)
{
    const float* Q  = (const float*)d_in[0];
    const float* K  = (const float*)d_in[1];
    const float* Vv = (const float*)d_in[2];

    float* out  = (float*)d_out;
    float* Vout = out;
    float* Aout = out + (size_t)BB * NN * DD;         // A region (scratch until phase 3)
    float* Gout = Aout + (size_t)BB * NN * SS;        // gates region (scores scratch)

    // fp16 split operands live in the A region until sparse_fused overwrites it
    __half* Qc = (__half*)Aout;
    __half* Kc = Qc + (size_t)BB * NN * KTOT;         // 96 MB total < 256 MB region

    const int QK_SMEM = 2 * (BM + BN) * LDSH * 2;     // 73,728 B
    cudaFuncSetAttribute(qk_hmma, cudaFuncAttributeMaxDynamicSharedMemorySize, QK_SMEM);

    // 1) split-convert Q,K to fp16 [hi|lo|hi] / [hi|hi|lo]
    convert_kernel<<<(unsigned)((size_t)BB * NN * DD / 4 / 256), 256>>>(Q, K, Qc, Kc);

    // 2) scores = Q'' K''^T via HMMA -> gates region
    dim3 g1(SS / BN, NN / BM, BB);
    qk_hmma<<<g1, 256, QK_SMEM>>>(Qc, Kc, Gout);

    // 3) fused sparsemax + AV gather + gate/A writes
    sparse_fused<<<BB * NN / 8, 256>>>(Gout, Aout, Vout, Vv);
}

// round 6
// speedup vs baseline: 4.0717x; 1.0606x over previous
#include <cuda_runtime.h>
#include <cuda_fp16.h>
#include <cstdint>

#define BB 16
#define NN 2048
#define SS 2048
#define DD 256

#define KTOT 768      // fp16-split GEMM depth: [hi|lo|hi] x [hi|hi|lo]
#define BM 128
#define BN 128
#define BKH 64        // K-chunk in halves
#define LDSH 72       // smem row stride in halves (+8 pad)

#define NTILE (SS / BN)   // 16 column tiles per row
#define NSLOT 8           // candidate slots per (row, tile)

// Candidate scratch (static device arrays: allocation-free, rewritten each run)
__device__ float d_cval[(size_t)BB * NN * NTILE * NSLOT];
__device__ int   d_cidx[(size_t)BB * NN * NTILE * NSLOT];
__device__ int   d_ccnt[(size_t)BB * NN * NTILE];

__device__ __forceinline__ uint32_t smem_u32(const void* p) {
    uint32_t a;
    asm("{ .reg .u64 t; cvta.to.shared.u64 t, %1; cvt.u32.u64 %0, t; }"
        : "=r"(a) : "l"(p));
    return a;
}

__device__ __forceinline__ void cp16(uint32_t dst, const void* src) {
    asm volatile("cp.async.cg.shared.global [%0], [%1], 16;" :: "r"(dst), "l"(src));
}

// ---------------------------------------------------------------------------
// Pre-convert: Q'' = [Qh | Ql | Qh], K'' = [Kh | Kh | Kl]  (fp16, K=768)
// ---------------------------------------------------------------------------
__global__ __launch_bounds__(256) void convert_kernel(
    const float* __restrict__ Q, const float* __restrict__ K,
    __half* __restrict__ Qc, __half* __restrict__ Kc)
{
    const size_t v = (size_t)blockIdx.x * 256 + threadIdx.x; // < BB*NN*DD/4
    const size_t row = v >> 6;
    const int d = (int)(v & 63) * 4;

    float4 q = *(const float4*)(Q + row * DD + d);
    float4 k = *(const float4*)(K + row * DD + d);
    float qa[4] = {q.x, q.y, q.z, q.w};
    float ka[4] = {k.x, k.y, k.z, k.w};

    __half qh[4], ql[4], kh[4], kl[4];
#pragma unroll
    for (int e = 0; e < 4; ++e) {
        qh[e] = __float2half_rn(qa[e]);
        ql[e] = __float2half_rn(qa[e] - __half2float(qh[e]));
        kh[e] = __float2half_rn(ka[e]);
        kl[e] = __float2half_rn(ka[e] - __half2float(kh[e]));
    }
    uint2 qhp = *(uint2*)qh, qlp = *(uint2*)ql;
    uint2 khp = *(uint2*)kh, klp = *(uint2*)kl;

    __half* qd = Qc + row * KTOT + d;
    *(uint2*)(qd)       = qhp;
    *(uint2*)(qd + 256) = qlp;
    *(uint2*)(qd + 512) = qhp;

    __half* kd = Kc + row * KTOT + d;
    *(uint2*)(kd)       = khp;
    *(uint2*)(kd + 256) = khp;
    *(uint2*)(kd + 512) = klp;
}

// ---------------------------------------------------------------------------
// QK GEMM via HMMA + candidate-extraction epilogue (no score writes).
// CTA tile 128x128, 8 warps of 64x32, BK=64 halves, 2-stage cp.async.
// ---------------------------------------------------------------------------
__global__ __launch_bounds__(256) void qk_hmma(
    const __half* __restrict__ Qc, const __half* __restrict__ Kc)
{
    extern __shared__ __align__(16) char smraw[];
    __half* As = (__half*)smraw;          // [2][BM][LDSH]
    __half* Bs = As + 2 * BM * LDSH;      // [2][BN][LDSH]

    const int tid = threadIdx.x, wid = tid >> 5, lane = tid & 31;
    const int warp_m = wid & 1;
    const int warp_n = wid >> 1;
    const int b = blockIdx.z;
    const int rowBase = blockIdx.y * BM;
    const int colBase = blockIdx.x * BN;
    const int tileX = blockIdx.x;
    const __half* Qb = Qc + ((size_t)b * NN + rowBase) * KTOT;
    const __half* Kb = Kc + ((size_t)b * SS + colBase) * KTOT;
    const uint32_t asb = smem_u32(As);
    const uint32_t bsb = smem_u32(Bs);

    float acc[4][4][4];
#pragma unroll
    for (int mt = 0; mt < 4; ++mt)
#pragma unroll
        for (int nt = 0; nt < 4; ++nt)
#pragma unroll
            for (int e = 0; e < 4; ++e) acc[mt][nt][e] = 0.0f;

#define ISSUE_STAGE(st, k0) do {                                              \
        _Pragma("unroll")                                                     \
        for (int l = 0; l < 4; ++l) {                                         \
            int idx = tid + l * 256;                                          \
            int row = idx >> 3;                                               \
            int c8  = (idx & 7) * 8;                                          \
            cp16(asb + (uint32_t)(((st) * BM * LDSH + row * LDSH + c8) * 2),  \
                 Qb + (size_t)row * KTOT + (k0) + c8);                        \
            cp16(bsb + (uint32_t)(((st) * BN * LDSH + row * LDSH + c8) * 2),  \
                 Kb + (size_t)row * KTOT + (k0) + c8);                        \
        }                                                                     \
        asm volatile("cp.async.commit_group;" ::: "memory");                  \
    } while (0)

    ISSUE_STAGE(0, 0);
    const int NK = KTOT / BKH;   // 12

    for (int c = 0; c < NK; ++c) {
        if (c + 1 < NK) {
            ISSUE_STAGE((c + 1) & 1, (c + 1) * BKH);
            asm volatile("cp.async.wait_group 1;" ::: "memory");
        } else {
            asm volatile("cp.async.wait_group 0;" ::: "memory");
        }
        __syncthreads();

        const int st = c & 1;
        const uint32_t ab = asb + (uint32_t)(st * BM * LDSH * 2);
        const uint32_t bbs = bsb + (uint32_t)(st * BN * LDSH * 2);

#pragma unroll
        for (int ks = 0; ks < BKH / 16; ++ks) {
            uint32_t a[4][4];
#pragma unroll
            for (int mt = 0; mt < 4; ++mt) {
                uint32_t addr = ab + (uint32_t)((((warp_m * 64 + mt * 16 + (lane & 15)) * LDSH)
                                 + ks * 16 + (lane >> 4) * 8) * 2);
                asm volatile(
                    "ldmatrix.sync.aligned.m8n8.x4.shared.b16 {%0,%1,%2,%3}, [%4];"
                    : "=r"(a[mt][0]), "=r"(a[mt][1]), "=r"(a[mt][2]), "=r"(a[mt][3])
                    : "r"(addr));
            }
            uint32_t bf[4][2];
#pragma unroll
            for (int g = 0; g < 2; ++g) {
                uint32_t addr = bbs + (uint32_t)((((warp_n * 32 + g * 16 + (lane & 15)) * LDSH)
                                 + ks * 16 + (lane >> 4) * 8) * 2);
                uint32_t r0, r1, r2, r3;
                asm volatile(
                    "ldmatrix.sync.aligned.m8n8.x4.shared.b16 {%0,%1,%2,%3}, [%4];"
                    : "=r"(r0), "=r"(r1), "=r"(r2), "=r"(r3)
                    : "r"(addr));
                bf[g * 2][0] = r0; bf[g * 2][1] = r2;
                bf[g * 2 + 1][0] = r1; bf[g * 2 + 1][1] = r3;
            }
#pragma unroll
            for (int mt = 0; mt < 4; ++mt)
#pragma unroll
                for (int nt = 0; nt < 4; ++nt) {
                    asm volatile(
                        "mma.sync.aligned.m16n8k16.row.col.f32.f16.f16.f32 "
                        "{%0,%1,%2,%3}, {%4,%5,%6,%7}, {%8,%9}, {%0,%1,%2,%3};"
                        : "+f"(acc[mt][nt][0]), "+f"(acc[mt][nt][1]),
                          "+f"(acc[mt][nt][2]), "+f"(acc[mt][nt][3])
                        : "r"(a[mt][0]), "r"(a[mt][1]), "r"(a[mt][2]), "r"(a[mt][3]),
                          "r"(bf[nt][0]), "r"(bf[nt][1]));
                }
        }
        __syncthreads();
    }
#undef ISSUE_STAGE

    // ---------------- Candidate-extraction epilogue --------------------
    // (smem repurposed; all mainloop reads done after final __syncthreads)
    float (*wmax)[4] = (float(*)[4])smraw;            // [128][4] per-warp_n row max
    float* tmax = (float*)(smraw + 128 * 4 * 4);      // [128] tile row max
    int*   scnt = (int*)(smraw + 128 * 4 * 4 + 512);  // [128] per-row counters

    // Per-warp row maxima: 4 lanes (lane&3) share a row -> shfl reduce
#pragma unroll
    for (int mt = 0; mt < 4; ++mt) {
#pragma unroll
        for (int h = 0; h < 2; ++h) {
            float rm = -1e30f;
#pragma unroll
            for (int nt = 0; nt < 4; ++nt)
                rm = fmaxf(rm, fmaxf(acc[mt][nt][h * 2], acc[mt][nt][h * 2 + 1]));
            rm = fmaxf(rm, __shfl_xor_sync(0xffffffffu, rm, 1));
            rm = fmaxf(rm, __shfl_xor_sync(0xffffffffu, rm, 2));
            if ((lane & 3) == 0)
                wmax[warp_m * 64 + mt * 16 + h * 8 + (lane >> 2)][warp_n] = rm;
        }
    }
    __syncthreads();
    if (tid < 128) {
        float t = fmaxf(fmaxf(wmax[tid][0], wmax[tid][1]),
                        fmaxf(wmax[tid][2], wmax[tid][3]));
        tmax[tid] = t;
        scnt[tid] = 0;
    }
    __syncthreads();

    // Extract elements > tile_rowmax - 1 into global candidate slots
#pragma unroll
    for (int mt = 0; mt < 4; ++mt) {
#pragma unroll
        for (int nt = 0; nt < 4; ++nt) {
#pragma unroll
            for (int e = 0; e < 4; ++e) {
                int r = warp_m * 64 + mt * 16 + ((e >> 1) ? 8 : 0) + (lane >> 2);
                float val = acc[mt][nt][e];
                if (val > tmax[r] - 1.0f) {
                    int pos = atomicAdd(&scnt[r], 1);
                    if (pos < NSLOT) {
                        size_t grow = (size_t)b * NN + rowBase + r;
                        size_t slot = (grow * NTILE + tileX) * NSLOT + pos;
                        d_cval[slot] = val;
                        d_cidx[slot] = colBase + warp_n * 32 + nt * 8
                                       + 2 * (lane & 3) + (e & 1);
                    }
                }
            }
        }
    }
    __syncthreads();
    if (tid < 128) {
        size_t grow = (size_t)b * NN + rowBase + tid;
        int cc = scnt[tid];
        d_ccnt[grow * NTILE + tileX] = cc < NSLOT ? cc : NSLOT;
    }
}

// ================= Fused sparsemax + AV-gather + gate writes ===============
// One warp per row; candidates come from the per-tile lists (no score reads).
__global__ void __launch_bounds__(256) sparse_fused(
    float* __restrict__ G, float* __restrict__ A,
    float* __restrict__ Vout, const float* __restrict__ Vals)
{
    __shared__ float cv[8][32];
    __shared__ int   ci[8][32];

    const int tid = threadIdx.x, wid = tid >> 5, lane = tid & 31;
    const int row = blockIdx.x * 8 + wid;       // 0..32767
    const int b = row >> 11;
    float* z = G + (size_t)row * SS;
    float* a = A + (size_t)row * SS;

    // Lanes 0..15 each own one tile's candidate list
    int cnt = 0;
    float tv[NSLOT];
    int   tix[NSLOT];
    if (lane < NTILE) {
        cnt = d_ccnt[(size_t)row * NTILE + lane];
        const size_t base = ((size_t)row * NTILE + lane) * NSLOT;
#pragma unroll
        for (int s = 0; s < NSLOT; ++s) {
            if (s < cnt) { tv[s] = d_cval[base + s]; tix[s] = d_cidx[base + s]; }
        }
    }

    // Global row max = max over all candidates (each tile's max is listed)
    float m = -1e30f;
#pragma unroll
    for (int s = 0; s < NSLOT; ++s)
        if (s < cnt) m = fmaxf(m, tv[s]);
#pragma unroll
    for (int o = 16; o > 0; o >>= 1) m = fmaxf(m, __shfl_xor_sync(0xffffffffu, m, o));
    const float thr = m - 1.0f;

    // Compact global candidates (val > thr) into shared lists
    int base = 0;
#pragma unroll
    for (int s = 0; s < NSLOT; ++s) {
        bool p = (s < cnt) && (tv[s] > thr);
        unsigned msk = __ballot_sync(0xffffffffu, p);
        if (p) {
            int pos = base + __popc(msk & ((1u << lane) - 1u));
            if (pos < 32) { cv[wid][pos] = tv[s]; ci[wid][pos] = tix[s]; }
        }
        base += __popc(msk);
    }
    const int mc = base > 32 ? 32 : base;
    __syncwarp();

    // Bisection for tau on candidates only (tau in [m-1, m])
    float cand = (lane < mc) ? cv[wid][lane] : -1e30f;
    float lo = thr, hi = m;
    for (int it = 0; it < 20; ++it) {
        float mid = 0.5f * (lo + hi);
        float s = fmaxf(cand - mid, 0.0f);
#pragma unroll
        for (int o = 16; o > 0; o >>= 1) s += __shfl_xor_sync(0xffffffffu, s, o);
        if (s >= 1.0f) lo = mid; else hi = mid;
    }
    // Exact tau from identified support {cand > lo}
    float inz = (cand > lo) ? cand : 0.0f;
    float inc = (cand > lo) ? 1.0f : 0.0f;
#pragma unroll
    for (int o = 16; o > 0; o >>= 1) {
        inz += __shfl_xor_sync(0xffffffffu, inz, o);
        inc += __shfl_xor_sync(0xffffffffu, inc, o);
    }
    const float tau = (inz - 1.0f) / inc;
    const float g = fmaxf(cand - tau, 0.0f);

    // V[row,:] = sum_i g_i * Vals[b, s_i, :]
    float4 acc0 = make_float4(0.f, 0.f, 0.f, 0.f);
    float4 acc1 = make_float4(0.f, 0.f, 0.f, 0.f);
    for (int i = 0; i < mc; ++i) {
        float gi = __shfl_sync(0xffffffffu, g, i);
        if (gi > 0.0f) {
            const float4* vr = (const float4*)(Vals + ((size_t)b * SS + ci[wid][i]) * DD + lane * 8);
            float4 p0 = vr[0], p1 = vr[1];
            acc0.x += gi * p0.x; acc0.y += gi * p0.y; acc0.z += gi * p0.z; acc0.w += gi * p0.w;
            acc1.x += gi * p1.x; acc1.y += gi * p1.y; acc1.z += gi * p1.z; acc1.w += gi * p1.w;
        }
    }
    float4* vo = (float4*)(Vout + (size_t)row * DD + lane * 8);
    vo[0] = acc0; vo[1] = acc1;

    // Gates: zero-fill both outputs, then scatter the few nonzeros.
    const float4 z4 = make_float4(0.f, 0.f, 0.f, 0.f);
#pragma unroll
    for (int j = 0; j < 16; ++j) {
        *(float4*)&z[(j * 32 + lane) * 4] = z4;
        *(float4*)&a[(j * 32 + lane) * 4] = z4;
    }
    __syncwarp();
    if (lane < mc && g > 0.0f) {
        int s = ci[wid][lane];
        z[s] = g;
        a[s] = g;
    }
}

// ============================== launch =====================================
extern "C" void kernel_launch(void* const* d_in, const int* in_sizes, int n_in,
                              void* d_out, int out_size)
{
    const float* Q  = (const float*)d_in[0];
    const float* K  = (const float*)d_in[1];
    const float* Vv = (const float*)d_in[2];

    float* out  = (float*)d_out;
    float* Vout = out;
    float* Aout = out + (size_t)BB * NN * DD;         // A region (scratch until phase 3)
    float* Gout = Aout + (size_t)BB * NN * SS;        // gates region

    // fp16 split operands live in the A region until sparse_fused overwrites it
    __half* Qc = (__half*)Aout;
    __half* Kc = Qc + (size_t)BB * NN * KTOT;

    const int QK_SMEM = 2 * (BM + BN) * LDSH * 2;     // 73,728 B
    cudaFuncSetAttribute(qk_hmma, cudaFuncAttributeMaxDynamicSharedMemorySize, QK_SMEM);

    // 1) split-convert Q,K to fp16 [hi|lo|hi] / [hi|hi|lo]
    convert_kernel<<<(unsigned)((size_t)BB * NN * DD / 4 / 256), 256>>>(Q, K, Qc, Kc);

    // 2) scores via HMMA -> per-tile candidate lists only (no score writes)
    dim3 g1(SS / BN, NN / BM, BB);
    qk_hmma<<<g1, 256, QK_SMEM>>>(Qc, Kc);

    // 3) fused sparsemax + AV gather + gate/A writes
    sparse_fused<<<BB * NN / 8, 256>>>(Gout, Aout, Vout, Vv);
}

// round 7
// speedup vs baseline: 7.3377x; 1.8021x over previous
#include <cuda_runtime.h>
#include <cuda_fp16.h>
#include <cstdint>

#define BB 16
#define NN 2048
#define SS 2048
#define DD 256

#define KQK 256       // hi-only fp16 GEMM depth
#define BM 128
#define BN 128
#define BKH 64        // K-chunk in halves
#define LDSH 72       // smem row stride in halves (+8 pad)

#define NTILE (SS / BN)   // 16 column tiles per row
#define NSLOT 8           // candidate slots per (row, tile)
#define MARGIN 0.1f       // approx-score safety margin (~12 sigma)

// Candidate scratch (static device arrays: allocation-free, rewritten each run)
__device__ float d_cval[(size_t)BB * NN * NTILE * NSLOT];
__device__ int   d_cidx[(size_t)BB * NN * NTILE * NSLOT];
__device__ int   d_ccnt[(size_t)BB * NN * NTILE];

__device__ __forceinline__ uint32_t smem_u32(const void* p) {
    uint32_t a;
    asm("{ .reg .u64 t; cvta.to.shared.u64 t, %1; cvt.u32.u64 %0, t; }"
        : "=r"(a) : "l"(p));
    return a;
}

__device__ __forceinline__ void cp16(uint32_t dst, const void* src) {
    asm volatile("cp.async.cg.shared.global [%0], [%1], 16;" :: "r"(dst), "l"(src));
}

// ---------------------------------------------------------------------------
// Pre-convert: Qc/Kc = fp16(Q), fp16(K)  (hi parts only, K=256)
// ---------------------------------------------------------------------------
__global__ __launch_bounds__(256) void convert_kernel(
    const float* __restrict__ Q, const float* __restrict__ K,
    __half* __restrict__ Qc, __half* __restrict__ Kc)
{
    const size_t v = (size_t)blockIdx.x * 256 + threadIdx.x; // < BB*NN*DD/4
    const size_t row = v >> 6;
    const int d = (int)(v & 63) * 4;

    float4 q = *(const float4*)(Q + row * DD + d);
    float4 k = *(const float4*)(K + row * DD + d);

    __half qh[4] = {__float2half_rn(q.x), __float2half_rn(q.y),
                    __float2half_rn(q.z), __float2half_rn(q.w)};
    __half kh[4] = {__float2half_rn(k.x), __float2half_rn(k.y),
                    __float2half_rn(k.z), __float2half_rn(k.w)};
    *(uint2*)(Qc + row * KQK + d) = *(uint2*)qh;
    *(uint2*)(Kc + row * KQK + d) = *(uint2*)kh;
}

// ---------------------------------------------------------------------------
// Approx QK GEMM via HMMA (hi*hi only) + candidate-extraction epilogue.
// CTA tile 128x128, 8 warps of 64x32, BK=64 halves, 2-stage cp.async,
// 2 CTAs/SM for latency hiding.
// ---------------------------------------------------------------------------
__global__ void __launch_bounds__(256, 2) qk_hmma(
    const __half* __restrict__ Qc, const __half* __restrict__ Kc)
{
    extern __shared__ __align__(16) char smraw[];
    __half* As = (__half*)smraw;          // [2][BM][LDSH]
    __half* Bs = As + 2 * BM * LDSH;      // [2][BN][LDSH]

    const int tid = threadIdx.x, wid = tid >> 5, lane = tid & 31;
    const int warp_m = wid & 1;
    const int warp_n = wid >> 1;
    const int b = blockIdx.z;
    const int rowBase = blockIdx.y * BM;
    const int colBase = blockIdx.x * BN;
    const int tileX = blockIdx.x;
    const __half* Qb = Qc + ((size_t)b * NN + rowBase) * KQK;
    const __half* Kb = Kc + ((size_t)b * SS + colBase) * KQK;
    const uint32_t asb = smem_u32(As);
    const uint32_t bsb = smem_u32(Bs);

    float acc[4][4][4];
#pragma unroll
    for (int mt = 0; mt < 4; ++mt)
#pragma unroll
        for (int nt = 0; nt < 4; ++nt)
#pragma unroll
            for (int e = 0; e < 4; ++e) acc[mt][nt][e] = 0.0f;

#define ISSUE_STAGE(st, k0) do {                                              \
        _Pragma("unroll")                                                     \
        for (int l = 0; l < 4; ++l) {                                         \
            int idx = tid + l * 256;                                          \
            int row = idx >> 3;                                               \
            int c8  = (idx & 7) * 8;                                          \
            cp16(asb + (uint32_t)(((st) * BM * LDSH + row * LDSH + c8) * 2),  \
                 Qb + (size_t)row * KQK + (k0) + c8);                         \
            cp16(bsb + (uint32_t)(((st) * BN * LDSH + row * LDSH + c8) * 2),  \
                 Kb + (size_t)row * KQK + (k0) + c8);                         \
        }                                                                     \
        asm volatile("cp.async.commit_group;" ::: "memory");                  \
    } while (0)

    ISSUE_STAGE(0, 0);
    const int NK = KQK / BKH;   // 4

    for (int c = 0; c < NK; ++c) {
        if (c + 1 < NK) {
            ISSUE_STAGE((c + 1) & 1, (c + 1) * BKH);
            asm volatile("cp.async.wait_group 1;" ::: "memory");
        } else {
            asm volatile("cp.async.wait_group 0;" ::: "memory");
        }
        __syncthreads();

        const int st = c & 1;
        const uint32_t ab = asb + (uint32_t)(st * BM * LDSH * 2);
        const uint32_t bbs = bsb + (uint32_t)(st * BN * LDSH * 2);

#pragma unroll
        for (int ks = 0; ks < BKH / 16; ++ks) {
            uint32_t a[4][4];
#pragma unroll
            for (int mt = 0; mt < 4; ++mt) {
                uint32_t addr = ab + (uint32_t)((((warp_m * 64 + mt * 16 + (lane & 15)) * LDSH)
                                 + ks * 16 + (lane >> 4) * 8) * 2);
                asm volatile(
                    "ldmatrix.sync.aligned.m8n8.x4.shared.b16 {%0,%1,%2,%3}, [%4];"
                    : "=r"(a[mt][0]), "=r"(a[mt][1]), "=r"(a[mt][2]), "=r"(a[mt][3])
                    : "r"(addr));
            }
            uint32_t bf[4][2];
#pragma unroll
            for (int g = 0; g < 2; ++g) {
                uint32_t addr = bbs + (uint32_t)((((warp_n * 32 + g * 16 + (lane & 15)) * LDSH)
                                 + ks * 16 + (lane >> 4) * 8) * 2);
                uint32_t r0, r1, r2, r3;
                asm volatile(
                    "ldmatrix.sync.aligned.m8n8.x4.shared.b16 {%0,%1,%2,%3}, [%4];"
                    : "=r"(r0), "=r"(r1), "=r"(r2), "=r"(r3)
                    : "r"(addr));
                bf[g * 2][0] = r0; bf[g * 2][1] = r2;
                bf[g * 2 + 1][0] = r1; bf[g * 2 + 1][1] = r3;
            }
#pragma unroll
            for (int mt = 0; mt < 4; ++mt)
#pragma unroll
                for (int nt = 0; nt < 4; ++nt) {
                    asm volatile(
                        "mma.sync.aligned.m16n8k16.row.col.f32.f16.f16.f32 "
                        "{%0,%1,%2,%3}, {%4,%5,%6,%7}, {%8,%9}, {%0,%1,%2,%3};"
                        : "+f"(acc[mt][nt][0]), "+f"(acc[mt][nt][1]),
                          "+f"(acc[mt][nt][2]), "+f"(acc[mt][nt][3])
                        : "r"(a[mt][0]), "r"(a[mt][1]), "r"(a[mt][2]), "r"(a[mt][3]),
                          "r"(bf[nt][0]), "r"(bf[nt][1]));
                }
        }
        __syncthreads();
    }
#undef ISSUE_STAGE

    // ---------------- Candidate-extraction epilogue --------------------
    float (*wmax)[4] = (float(*)[4])smraw;            // [128][4]
    float* tmax = (float*)(smraw + 128 * 4 * 4);      // [128]
    int*   scnt = (int*)(smraw + 128 * 4 * 4 + 512);  // [128]

#pragma unroll
    for (int mt = 0; mt < 4; ++mt) {
#pragma unroll
        for (int h = 0; h < 2; ++h) {
            float rm = -1e30f;
#pragma unroll
            for (int nt = 0; nt < 4; ++nt)
                rm = fmaxf(rm, fmaxf(acc[mt][nt][h * 2], acc[mt][nt][h * 2 + 1]));
            rm = fmaxf(rm, __shfl_xor_sync(0xffffffffu, rm, 1));
            rm = fmaxf(rm, __shfl_xor_sync(0xffffffffu, rm, 2));
            if ((lane & 3) == 0)
                wmax[warp_m * 64 + mt * 16 + h * 8 + (lane >> 2)][warp_n] = rm;
        }
    }
    __syncthreads();
    if (tid < 128) {
        float t = fmaxf(fmaxf(wmax[tid][0], wmax[tid][1]),
                        fmaxf(wmax[tid][2], wmax[tid][3]));
        tmax[tid] = t;
        scnt[tid] = 0;
    }
    __syncthreads();

    // Extract elements > tile_rowmax - 1 - MARGIN (superset under fp16 error)
#pragma unroll
    for (int mt = 0; mt < 4; ++mt) {
#pragma unroll
        for (int nt = 0; nt < 4; ++nt) {
#pragma unroll
            for (int e = 0; e < 4; ++e) {
                int r = warp_m * 64 + mt * 16 + ((e >> 1) ? 8 : 0) + (lane >> 2);
                float val = acc[mt][nt][e];
                if (val > tmax[r] - 1.0f - MARGIN) {
                    int pos = atomicAdd(&scnt[r], 1);
                    if (pos < NSLOT) {
                        size_t grow = (size_t)b * NN + rowBase + r;
                        size_t slot = (grow * NTILE + tileX) * NSLOT + pos;
                        d_cval[slot] = val;
                        d_cidx[slot] = colBase + warp_n * 32 + nt * 8
                                       + 2 * (lane & 3) + (e & 1);
                    }
                }
            }
        }
    }
    __syncthreads();
    if (tid < 128) {
        size_t grow = (size_t)b * NN + rowBase + tid;
        int cc = scnt[tid];
        d_ccnt[grow * NTILE + tileX] = cc < NSLOT ? cc : NSLOT;
    }
}

// ======= Fused exact-rescore + sparsemax + AV-gather + gate writes =========
// One warp per row. Approx candidates -> exact fp32 dot products -> sparsemax.
__global__ void __launch_bounds__(256) sparse_fused(
    const float* __restrict__ Q, const float* __restrict__ Kk,
    float* __restrict__ G, float* __restrict__ A,
    float* __restrict__ Vout, const float* __restrict__ Vals)
{
    __shared__ float cv[8][32];
    __shared__ int   ci[8][32];

    const int tid = threadIdx.x, wid = tid >> 5, lane = tid & 31;
    const int row = blockIdx.x * 8 + wid;       // 0..32767
    const int b = row >> 11;
    float* z = G + (size_t)row * SS;
    float* a = A + (size_t)row * SS;

    // Lanes 0..15 each own one tile's candidate list (approx values)
    int cnt = 0;
    float tv[NSLOT];
    int   tix[NSLOT];
    if (lane < NTILE) {
        cnt = d_ccnt[(size_t)row * NTILE + lane];
        const size_t base = ((size_t)row * NTILE + lane) * NSLOT;
#pragma unroll
        for (int s = 0; s < NSLOT; ++s) {
            if (s < cnt) { tv[s] = d_cval[base + s]; tix[s] = d_cidx[base + s]; }
        }
    }

    // Approx global row max
    float m = -1e30f;
#pragma unroll
    for (int s = 0; s < NSLOT; ++s)
        if (s < cnt) m = fmaxf(m, tv[s]);
#pragma unroll
    for (int o = 16; o > 0; o >>= 1) m = fmaxf(m, __shfl_xor_sync(0xffffffffu, m, o));
    const float thr = m - 1.0f - MARGIN;

    // Compact survivors (approx val > thr) into shared lists
    int base = 0;
#pragma unroll
    for (int s = 0; s < NSLOT; ++s) {
        bool p = (s < cnt) && (tv[s] > thr);
        unsigned msk = __ballot_sync(0xffffffffu, p);
        if (p) {
            int pos = base + __popc(msk & ((1u << lane) - 1u));
            if (pos < 32) { ci[wid][pos] = tix[s]; }
        }
        base += __popc(msk);
    }
    const int mc = base > 32 ? 32 : base;
    __syncwarp();

    // Exact fp32 rescoring of survivors: warp-cooperative dot products
    const float* Qr = Q + (size_t)row * DD;
    float4 q0 = ((const float4*)Qr)[lane * 2];
    float4 q1 = ((const float4*)Qr)[lane * 2 + 1];
    for (int i = 0; i < mc; ++i) {
        const float* Kr = Kk + ((size_t)b * SS + ci[wid][i]) * DD;
        float4 k0 = ((const float4*)Kr)[lane * 2];
        float4 k1 = ((const float4*)Kr)[lane * 2 + 1];
        float p = q0.x * k0.x + q0.y * k0.y + q0.z * k0.z + q0.w * k0.w
                + q1.x * k1.x + q1.y * k1.y + q1.z * k1.z + q1.w * k1.w;
#pragma unroll
        for (int o = 16; o > 0; o >>= 1) p += __shfl_xor_sync(0xffffffffu, p, o);
        cv[wid][i] = p;   // same value in all lanes
    }
    __syncwarp();

    // Sparsemax on exact candidate scores
    float cand = (lane < mc) ? cv[wid][lane] : -1e30f;
    float me = cand;
#pragma unroll
    for (int o = 16; o > 0; o >>= 1) me = fmaxf(me, __shfl_xor_sync(0xffffffffu, me, o));
    float lo = me - 1.0f, hi = me;
    for (int it = 0; it < 20; ++it) {
        float mid = 0.5f * (lo + hi);
        float s = fmaxf(cand - mid, 0.0f);
#pragma unroll
        for (int o = 16; o > 0; o >>= 1) s += __shfl_xor_sync(0xffffffffu, s, o);
        if (s >= 1.0f) lo = mid; else hi = mid;
    }
    float inz = (cand > lo) ? cand : 0.0f;
    float inc = (cand > lo) ? 1.0f : 0.0f;
#pragma unroll
    for (int o = 16; o > 0; o >>= 1) {
        inz += __shfl_xor_sync(0xffffffffu, inz, o);
        inc += __shfl_xor_sync(0xffffffffu, inc, o);
    }
    const float tau = (inz - 1.0f) / inc;
    const float g = fmaxf(cand - tau, 0.0f);

    // V[row,:] = sum_i g_i * Vals[b, s_i, :]
    float4 acc0 = make_float4(0.f, 0.f, 0.f, 0.f);
    float4 acc1 = make_float4(0.f, 0.f, 0.f, 0.f);
    for (int i = 0; i < mc; ++i) {
        float gi = __shfl_sync(0xffffffffu, g, i);
        if (gi > 0.0f) {
            const float4* vr = (const float4*)(Vals + ((size_t)b * SS + ci[wid][i]) * DD + lane * 8);
            float4 p0 = vr[0], p1 = vr[1];
            acc0.x += gi * p0.x; acc0.y += gi * p0.y; acc0.z += gi * p0.z; acc0.w += gi * p0.w;
            acc1.x += gi * p1.x; acc1.y += gi * p1.y; acc1.z += gi * p1.z; acc1.w += gi * p1.w;
        }
    }
    float4* vo = (float4*)(Vout + (size_t)row * DD + lane * 8);
    vo[0] = acc0; vo[1] = acc1;

    // Gates: zero-fill both outputs, then scatter the few nonzeros.
    const float4 z4 = make_float4(0.f, 0.f, 0.f, 0.f);
#pragma unroll
    for (int j = 0; j < 16; ++j) {
        *(float4*)&z[(j * 32 + lane) * 4] = z4;
        *(float4*)&a[(j * 32 + lane) * 4] = z4;
    }
    __syncwarp();
    if (lane < mc && g > 0.0f) {
        int s = ci[wid][lane];
        z[s] = g;
        a[s] = g;
    }
}

// ============================== launch =====================================
extern "C" void kernel_launch(void* const* d_in, const int* in_sizes, int n_in,
                              void* d_out, int out_size)
{
    const float* Q  = (const float*)d_in[0];
    const float* K  = (const float*)d_in[1];
    const float* Vv = (const float*)d_in[2];

    float* out  = (float*)d_out;
    float* Vout = out;
    float* Aout = out + (size_t)BB * NN * DD;         // A region (scratch until phase 3)
    float* Gout = Aout + (size_t)BB * NN * SS;        // gates region

    // fp16 hi operands live in the A region until sparse_fused overwrites it
    __half* Qc = (__half*)Aout;
    __half* Kc = Qc + (size_t)BB * NN * KQK;          // 32 MB total

    const int QK_SMEM = 2 * (BM + BN) * LDSH * 2;     // 73,728 B
    cudaFuncSetAttribute(qk_hmma, cudaFuncAttributeMaxDynamicSharedMemorySize, QK_SMEM);

    // 1) convert Q,K to fp16 (hi only)
    convert_kernel<<<(unsigned)((size_t)BB * NN * DD / 4 / 256), 256>>>(Q, K, Qc, Kc);

    // 2) approx scores via HMMA -> per-tile candidate lists (no score writes)
    dim3 g1(SS / BN, NN / BM, BB);
    qk_hmma<<<g1, 256, QK_SMEM>>>(Qc, Kc);

    // 3) exact rescore + sparsemax + AV gather + gate/A writes
    sparse_fused<<<BB * NN / 8, 256>>>(Q, K, Gout, Aout, Vout, Vv);
}

// round 8
// speedup vs baseline: 7.6933x; 1.0485x over previous
#include <cuda_runtime.h>
#include <cuda_fp16.h>
#include <cstdint>

#define BB 16
#define NN 2048
#define SS 2048
#define DD 256

#define KQK 256       // hi-only fp16 GEMM depth
#define BM 128
#define BN 128
#define BKH 64        // K-chunk in halves
#define LDSH 72       // smem row stride in halves (+8 pad)

#define NTILE (SS / BN)   // 16 column tiles per row
#define NSLOT 8           // candidate slots per (row, tile)
#define MARGIN 0.1f       // approx-score safety margin (~12 sigma)

// Static device scratch (allocation-free, fully rewritten each run)
__device__ float  d_cval[(size_t)BB * NN * NTILE * NSLOT];
__device__ int    d_cidx[(size_t)BB * NN * NTILE * NSLOT];
__device__ int    d_ccnt[(size_t)BB * NN * NTILE];
__device__ __half d_qc[(size_t)BB * NN * KQK];
__device__ __half d_kc[(size_t)BB * SS * KQK];

__device__ __forceinline__ uint32_t smem_u32(const void* p) {
    uint32_t a;
    asm("{ .reg .u64 t; cvta.to.shared.u64 t, %1; cvt.u32.u64 %0, t; }"
        : "=r"(a) : "l"(p));
    return a;
}

__device__ __forceinline__ void cp16(uint32_t dst, const void* src) {
    asm volatile("cp.async.cg.shared.global [%0], [%1], 16;" :: "r"(dst), "l"(src));
}

// ---------------------------------------------------------------------------
// Pre-convert: d_qc/d_kc = fp16(Q), fp16(K)  (hi parts only)
// ---------------------------------------------------------------------------
__global__ __launch_bounds__(256) void convert_kernel(
    const float* __restrict__ Q, const float* __restrict__ K)
{
    const size_t v = (size_t)blockIdx.x * 256 + threadIdx.x; // < BB*NN*DD/4
    const size_t row = v >> 6;
    const int d = (int)(v & 63) * 4;

    float4 q = *(const float4*)(Q + row * DD + d);
    float4 k = *(const float4*)(K + row * DD + d);

    __half qh[4] = {__float2half_rn(q.x), __float2half_rn(q.y),
                    __float2half_rn(q.z), __float2half_rn(q.w)};
    __half kh[4] = {__float2half_rn(k.x), __float2half_rn(k.y),
                    __float2half_rn(k.z), __float2half_rn(k.w)};
    *(uint2*)(d_qc + row * KQK + d) = *(uint2*)qh;
    *(uint2*)(d_kc + row * KQK + d) = *(uint2*)kh;
}

// ---------------------------------------------------------------------------
// Approx QK GEMM via HMMA (hi*hi) + zero-fill of output gate tiles (overlapped
// under the MMA mainloop) + candidate-extraction epilogue.
// CTA tile 128x128, 8 warps of 64x32, BK=64 halves, 2-stage cp.async.
// ---------------------------------------------------------------------------
__global__ void __launch_bounds__(256, 2) qk_hmma(
    float* __restrict__ G, float* __restrict__ A)
{
    extern __shared__ __align__(16) char smraw[];
    __half* As = (__half*)smraw;          // [2][BM][LDSH]
    __half* Bs = As + 2 * BM * LDSH;      // [2][BN][LDSH]

    const int tid = threadIdx.x, wid = tid >> 5, lane = tid & 31;
    const int warp_m = wid & 1;
    const int warp_n = wid >> 1;
    const int b = blockIdx.z;
    const int rowBase = blockIdx.y * BM;
    const int colBase = blockIdx.x * BN;
    const int tileX = blockIdx.x;
    const __half* Qb = d_qc + ((size_t)b * NN + rowBase) * KQK;
    const __half* Kb = d_kc + ((size_t)b * SS + colBase) * KQK;
    const uint32_t asb = smem_u32(As);
    const uint32_t bsb = smem_u32(Bs);

    float acc[4][4][4];
#pragma unroll
    for (int mt = 0; mt < 4; ++mt)
#pragma unroll
        for (int nt = 0; nt < 4; ++nt)
#pragma unroll
            for (int e = 0; e < 4; ++e) acc[mt][nt][e] = 0.0f;

#define ISSUE_STAGE(st, k0) do {                                              \
        _Pragma("unroll")                                                     \
        for (int l = 0; l < 4; ++l) {                                         \
            int idx = tid + l * 256;                                          \
            int row = idx >> 3;                                               \
            int c8  = (idx & 7) * 8;                                          \
            cp16(asb + (uint32_t)(((st) * BM * LDSH + row * LDSH + c8) * 2),  \
                 Qb + (size_t)row * KQK + (k0) + c8);                         \
            cp16(bsb + (uint32_t)(((st) * BN * LDSH + row * LDSH + c8) * 2),  \
                 Kb + (size_t)row * KQK + (k0) + c8);                         \
        }                                                                     \
        asm volatile("cp.async.commit_group;" ::: "memory");                  \
    } while (0)

    ISSUE_STAGE(0, 0);

    // Zero-fill this CTA's 128x128 tile of G and A (fire-and-forget stores,
    // drained by the memory system underneath the MMA mainloop).
    {
        const float4 z4 = make_float4(0.f, 0.f, 0.f, 0.f);
        float* Gt = G + ((size_t)b * NN + rowBase) * SS + colBase;
        float* At = A + ((size_t)b * NN + rowBase) * SS + colBase;
#pragma unroll
        for (int l = 0; l < 16; ++l) {
            int f = tid + l * 256;        // 0..4095 float4 positions
            int row = f >> 5;             // 32 float4 per 128-col row
            int c4 = (f & 31) * 4;
            *(float4*)(Gt + (size_t)row * SS + c4) = z4;
            *(float4*)(At + (size_t)row * SS + c4) = z4;
        }
    }

    const int NK = KQK / BKH;   // 4
    for (int c = 0; c < NK; ++c) {
        if (c + 1 < NK) {
            ISSUE_STAGE((c + 1) & 1, (c + 1) * BKH);
            asm volatile("cp.async.wait_group 1;" ::: "memory");
        } else {
            asm volatile("cp.async.wait_group 0;" ::: "memory");
        }
        __syncthreads();

        const int st = c & 1;
        const uint32_t ab = asb + (uint32_t)(st * BM * LDSH * 2);
        const uint32_t bbs = bsb + (uint32_t)(st * BN * LDSH * 2);

#pragma unroll
        for (int ks = 0; ks < BKH / 16; ++ks) {
            uint32_t a[4][4];
#pragma unroll
            for (int mt = 0; mt < 4; ++mt) {
                uint32_t addr = ab + (uint32_t)((((warp_m * 64 + mt * 16 + (lane & 15)) * LDSH)
                                 + ks * 16 + (lane >> 4) * 8) * 2);
                asm volatile(
                    "ldmatrix.sync.aligned.m8n8.x4.shared.b16 {%0,%1,%2,%3}, [%4];"
                    : "=r"(a[mt][0]), "=r"(a[mt][1]), "=r"(a[mt][2]), "=r"(a[mt][3])
                    : "r"(addr));
            }
            uint32_t bf[4][2];
#pragma unroll
            for (int g = 0; g < 2; ++g) {
                uint32_t addr = bbs + (uint32_t)((((warp_n * 32 + g * 16 + (lane & 15)) * LDSH)
                                 + ks * 16 + (lane >> 4) * 8) * 2);
                uint32_t r0, r1, r2, r3;
                asm volatile(
                    "ldmatrix.sync.aligned.m8n8.x4.shared.b16 {%0,%1,%2,%3}, [%4];"
                    : "=r"(r0), "=r"(r1), "=r"(r2), "=r"(r3)
                    : "r"(addr));
                bf[g * 2][0] = r0; bf[g * 2][1] = r2;
                bf[g * 2 + 1][0] = r1; bf[g * 2 + 1][1] = r3;
            }
#pragma unroll
            for (int mt = 0; mt < 4; ++mt)
#pragma unroll
                for (int nt = 0; nt < 4; ++nt) {
                    asm volatile(
                        "mma.sync.aligned.m16n8k16.row.col.f32.f16.f16.f32 "
                        "{%0,%1,%2,%3}, {%4,%5,%6,%7}, {%8,%9}, {%0,%1,%2,%3};"
                        : "+f"(acc[mt][nt][0]), "+f"(acc[mt][nt][1]),
                          "+f"(acc[mt][nt][2]), "+f"(acc[mt][nt][3])
                        : "r"(a[mt][0]), "r"(a[mt][1]), "r"(a[mt][2]), "r"(a[mt][3]),
                          "r"(bf[nt][0]), "r"(bf[nt][1]));
                }
        }
        __syncthreads();
    }
#undef ISSUE_STAGE

    // ---------------- Candidate-extraction epilogue --------------------
    float (*wmax)[4] = (float(*)[4])smraw;            // [128][4]
    float* tmax = (float*)(smraw + 128 * 4 * 4);      // [128]
    int*   scnt = (int*)(smraw + 128 * 4 * 4 + 512);  // [128]

#pragma unroll
    for (int mt = 0; mt < 4; ++mt) {
#pragma unroll
        for (int h = 0; h < 2; ++h) {
            float rm = -1e30f;
#pragma unroll
            for (int nt = 0; nt < 4; ++nt)
                rm = fmaxf(rm, fmaxf(acc[mt][nt][h * 2], acc[mt][nt][h * 2 + 1]));
            rm = fmaxf(rm, __shfl_xor_sync(0xffffffffu, rm, 1));
            rm = fmaxf(rm, __shfl_xor_sync(0xffffffffu, rm, 2));
            if ((lane & 3) == 0)
                wmax[warp_m * 64 + mt * 16 + h * 8 + (lane >> 2)][warp_n] = rm;
        }
    }
    __syncthreads();
    if (tid < 128) {
        float t = fmaxf(fmaxf(wmax[tid][0], wmax[tid][1]),
                        fmaxf(wmax[tid][2], wmax[tid][3]));
        tmax[tid] = t;
        scnt[tid] = 0;
    }
    __syncthreads();

    // Extract elements > tile_rowmax - 1 - MARGIN (superset under fp16 error)
#pragma unroll
    for (int mt = 0; mt < 4; ++mt) {
#pragma unroll
        for (int nt = 0; nt < 4; ++nt) {
#pragma unroll
            for (int e = 0; e < 4; ++e) {
                int r = warp_m * 64 + mt * 16 + ((e >> 1) ? 8 : 0) + (lane >> 2);
                float val = acc[mt][nt][e];
                if (val > tmax[r] - 1.0f - MARGIN) {
                    int pos = atomicAdd(&scnt[r], 1);
                    if (pos < NSLOT) {
                        size_t grow = (size_t)b * NN + rowBase + r;
                        size_t slot = (grow * NTILE + tileX) * NSLOT + pos;
                        d_cval[slot] = val;
                        d_cidx[slot] = colBase + warp_n * 32 + nt * 8
                                       + 2 * (lane & 3) + (e & 1);
                    }
                }
            }
        }
    }
    __syncthreads();
    if (tid < 128) {
        size_t grow = (size_t)b * NN + rowBase + tid;
        int cc = scnt[tid];
        d_ccnt[grow * NTILE + tileX] = cc < NSLOT ? cc : NSLOT;
    }
}

// ======= Fused exact-rescore + sparsemax + AV-gather + gate scatter ========
// One warp per row. Gate/A zeros were written by qk_hmma; only scatter here.
__global__ void __launch_bounds__(256) sparse_fused(
    const float* __restrict__ Q, const float* __restrict__ Kk,
    float* __restrict__ G, float* __restrict__ A,
    float* __restrict__ Vout, const float* __restrict__ Vals)
{
    __shared__ float cv[8][32];
    __shared__ int   ci[8][32];

    const int tid = threadIdx.x, wid = tid >> 5, lane = tid & 31;
    const int row = blockIdx.x * 8 + wid;       // 0..32767
    const int b = row >> 11;

    // Lanes 0..15 each own one tile's candidate list (approx values)
    int cnt = 0;
    float tv[NSLOT];
    int   tix[NSLOT];
    if (lane < NTILE) {
        cnt = d_ccnt[(size_t)row * NTILE + lane];
        const size_t base = ((size_t)row * NTILE + lane) * NSLOT;
#pragma unroll
        for (int s = 0; s < NSLOT; ++s) {
            if (s < cnt) { tv[s] = d_cval[base + s]; tix[s] = d_cidx[base + s]; }
        }
    }

    // Approx global row max
    float m = -1e30f;
#pragma unroll
    for (int s = 0; s < NSLOT; ++s)
        if (s < cnt) m = fmaxf(m, tv[s]);
#pragma unroll
    for (int o = 16; o > 0; o >>= 1) m = fmaxf(m, __shfl_xor_sync(0xffffffffu, m, o));
    const float thr = m - 1.0f - MARGIN;

    // Compact survivors (approx val > thr) into shared lists
    int base = 0;
#pragma unroll
    for (int s = 0; s < NSLOT; ++s) {
        bool p = (s < cnt) && (tv[s] > thr);
        unsigned msk = __ballot_sync(0xffffffffu, p);
        if (p) {
            int pos = base + __popc(msk & ((1u << lane) - 1u));
            if (pos < 32) { ci[wid][pos] = tix[s]; }
        }
        base += __popc(msk);
    }
    const int mc = base > 32 ? 32 : base;
    __syncwarp();

    // Exact fp32 rescoring of survivors: warp-cooperative dot products
    const float* Qr = Q + (size_t)row * DD;
    float4 q0 = ((const float4*)Qr)[lane * 2];
    float4 q1 = ((const float4*)Qr)[lane * 2 + 1];
    for (int i = 0; i < mc; ++i) {
        const float* Kr = Kk + ((size_t)b * SS + ci[wid][i]) * DD;
        float4 k0 = ((const float4*)Kr)[lane * 2];
        float4 k1 = ((const float4*)Kr)[lane * 2 + 1];
        float p = q0.x * k0.x + q0.y * k0.y + q0.z * k0.z + q0.w * k0.w
                + q1.x * k1.x + q1.y * k1.y + q1.z * k1.z + q1.w * k1.w;
#pragma unroll
        for (int o = 16; o > 0; o >>= 1) p += __shfl_xor_sync(0xffffffffu, p, o);
        cv[wid][i] = p;   // same value in all lanes
    }
    __syncwarp();

    // Sparsemax on exact candidate scores
    float cand = (lane < mc) ? cv[wid][lane] : -1e30f;
    float me = cand;
#pragma unroll
    for (int o = 16; o > 0; o >>= 1) me = fmaxf(me, __shfl_xor_sync(0xffffffffu, me, o));
    float lo = me - 1.0f, hi = me;
    for (int it = 0; it < 20; ++it) {
        float mid = 0.5f * (lo + hi);
        float s = fmaxf(cand - mid, 0.0f);
#pragma unroll
        for (int o = 16; o > 0; o >>= 1) s += __shfl_xor_sync(0xffffffffu, s, o);
        if (s >= 1.0f) lo = mid; else hi = mid;
    }
    float inz = (cand > lo) ? cand : 0.0f;
    float inc = (cand > lo) ? 1.0f : 0.0f;
#pragma unroll
    for (int o = 16; o > 0; o >>= 1) {
        inz += __shfl_xor_sync(0xffffffffu, inz, o);
        inc += __shfl_xor_sync(0xffffffffu, inc, o);
    }
    const float tau = (inz - 1.0f) / inc;
    const float g = fmaxf(cand - tau, 0.0f);

    // V[row,:] = sum_i g_i * Vals[b, s_i, :]
    float4 acc0 = make_float4(0.f, 0.f, 0.f, 0.f);
    float4 acc1 = make_float4(0.f, 0.f, 0.f, 0.f);
    for (int i = 0; i < mc; ++i) {
        float gi = __shfl_sync(0xffffffffu, g, i);
        if (gi > 0.0f) {
            const float4* vr = (const float4*)(Vals + ((size_t)b * SS + ci[wid][i]) * DD + lane * 8);
            float4 p0 = vr[0], p1 = vr[1];
            acc0.x += gi * p0.x; acc0.y += gi * p0.y; acc0.z += gi * p0.z; acc0.w += gi * p0.w;
            acc1.x += gi * p1.x; acc1.y += gi * p1.y; acc1.z += gi * p1.z; acc1.w += gi * p1.w;
        }
    }
    float4* vo = (float4*)(Vout + (size_t)row * DD + lane * 8);
    vo[0] = acc0; vo[1] = acc1;

    // Scatter nonzero gates (zeros pre-written by qk_hmma)
    if (lane < mc && g > 0.0f) {
        int s = ci[wid][lane];
        G[(size_t)row * SS + s] = g;
        A[(size_t)row * SS + s] = g;
    }
}

// ============================== launch =====================================
extern "C" void kernel_launch(void* const* d_in, const int* in_sizes, int n_in,
                              void* d_out, int out_size)
{
    const float* Q  = (const float*)d_in[0];
    const float* K  = (const float*)d_in[1];
    const float* Vv = (const float*)d_in[2];

    float* out  = (float*)d_out;
    float* Vout = out;
    float* Aout = out + (size_t)BB * NN * DD;
    float* Gout = Aout + (size_t)BB * NN * SS;

    const int QK_SMEM = 2 * (BM + BN) * LDSH * 2;     // 73,728 B
    cudaFuncSetAttribute(qk_hmma, cudaFuncAttributeMaxDynamicSharedMemorySize, QK_SMEM);

    // 1) convert Q,K to fp16 (hi only) into static scratch
    convert_kernel<<<(unsigned)((size_t)BB * NN * DD / 4 / 256), 256>>>(Q, K);

    // 2) approx scores via HMMA -> candidate lists; zero-fills G and A tiles
    dim3 g1(SS / BN, NN / BM, BB);
    qk_hmma<<<g1, 256, QK_SMEM>>>(Gout, Aout);

    // 3) exact rescore + sparsemax + AV gather + gate/A scatter
    sparse_fused<<<BB * NN / 8, 256>>>(Q, K, Gout, Aout, Vout, Vv);
}

// round 9
// speedup vs baseline: 8.2841x; 1.0768x over previous
#include <cuda_runtime.h>
#include <cuda_fp16.h>
#include <cstdint>

#define BB 16
#define NN 2048
#define SS 2048
#define DD 256

#define KQK 256       // hi-only fp16 GEMM depth
#define BM 128
#define BN 128
#define BKH 64        // K-chunk in halves
#define LDSH 72       // smem row stride in halves (+8 pad)

#define NTILE (SS / BN)   // 16 column tiles per row
#define NSLOT 8           // candidate slots per (row, tile)
#define MARGIN 0.1f       // approx-score safety margin (~12 sigma)

// Static device scratch (allocation-free, fully rewritten each run)
__device__ float  d_cval[(size_t)BB * NN * NTILE * NSLOT];
__device__ int    d_cidx[(size_t)BB * NN * NTILE * NSLOT];
__device__ int    d_ccnt[(size_t)BB * NN * NTILE];
__device__ __half d_qc[(size_t)BB * NN * KQK];
__device__ __half d_kc[(size_t)BB * SS * KQK];

__device__ __forceinline__ uint32_t smem_u32(const void* p) {
    uint32_t a;
    asm("{ .reg .u64 t; cvta.to.shared.u64 t, %1; cvt.u32.u64 %0, t; }"
        : "=r"(a) : "l"(p));
    return a;
}

__device__ __forceinline__ void cp16(uint32_t dst, const void* src) {
    asm volatile("cp.async.cg.shared.global [%0], [%1], 16;" :: "r"(dst), "l"(src));
}

// Streaming (evict-first) zero store: keeps fill traffic out of hot L2 sets.
__device__ __forceinline__ void stg_cs_zero16(float* p) {
    asm volatile("st.global.cs.v4.f32 [%0], {%1, %1, %1, %1};"
                 :: "l"(p), "f"(0.0f) : "memory");
}

// ---------------------------------------------------------------------------
// Pre-convert: d_qc/d_kc = fp16(Q), fp16(K)  (hi parts only)
// ---------------------------------------------------------------------------
__global__ __launch_bounds__(256) void convert_kernel(
    const float* __restrict__ Q, const float* __restrict__ K)
{
    const size_t v = (size_t)blockIdx.x * 256 + threadIdx.x; // < BB*NN*DD/4
    const size_t row = v >> 6;
    const int d = (int)(v & 63) * 4;

    float4 q = *(const float4*)(Q + row * DD + d);
    float4 k = *(const float4*)(K + row * DD + d);

    __half qh[4] = {__float2half_rn(q.x), __float2half_rn(q.y),
                    __float2half_rn(q.z), __float2half_rn(q.w)};
    __half kh[4] = {__float2half_rn(k.x), __float2half_rn(k.y),
                    __float2half_rn(k.z), __float2half_rn(k.w)};
    *(uint2*)(d_qc + row * KQK + d) = *(uint2*)qh;
    *(uint2*)(d_kc + row * KQK + d) = *(uint2*)kh;
}

// ---------------------------------------------------------------------------
// Approx QK GEMM via HMMA (hi*hi) + interleaved streaming zero-fill of the
// output gate tiles + candidate-extraction epilogue.
// CTA tile 128x128, 8 warps of 64x32, BK=64 halves, 2-stage cp.async.
// ---------------------------------------------------------------------------
__global__ void __launch_bounds__(256, 2) qk_hmma(
    float* __restrict__ G, float* __restrict__ A)
{
    extern __shared__ __align__(16) char smraw[];
    __half* As = (__half*)smraw;          // [2][BM][LDSH]
    __half* Bs = As + 2 * BM * LDSH;      // [2][BN][LDSH]

    const int tid = threadIdx.x, wid = tid >> 5, lane = tid & 31;
    const int warp_m = wid & 1;
    const int warp_n = wid >> 1;
    const int b = blockIdx.z;
    const int rowBase = blockIdx.y * BM;
    const int colBase = blockIdx.x * BN;
    const int tileX = blockIdx.x;
    const __half* Qb = d_qc + ((size_t)b * NN + rowBase) * KQK;
    const __half* Kb = d_kc + ((size_t)b * SS + colBase) * KQK;
    const uint32_t asb = smem_u32(As);
    const uint32_t bsb = smem_u32(Bs);

    float* Gt = G + ((size_t)b * NN + rowBase) * SS + colBase;
    float* At = A + ((size_t)b * NN + rowBase) * SS + colBase;

    float acc[4][4][4];
#pragma unroll
    for (int mt = 0; mt < 4; ++mt)
#pragma unroll
        for (int nt = 0; nt < 4; ++nt)
#pragma unroll
            for (int e = 0; e < 4; ++e) acc[mt][nt][e] = 0.0f;

#define ISSUE_STAGE(st, k0) do {                                              \
        _Pragma("unroll")                                                     \
        for (int l = 0; l < 4; ++l) {                                         \
            int idx = tid + l * 256;                                          \
            int row = idx >> 3;                                               \
            int c8  = (idx & 7) * 8;                                          \
            cp16(asb + (uint32_t)(((st) * BM * LDSH + row * LDSH + c8) * 2),  \
                 Qb + (size_t)row * KQK + (k0) + c8);                         \
            cp16(bsb + (uint32_t)(((st) * BN * LDSH + row * LDSH + c8) * 2),  \
                 Kb + (size_t)row * KQK + (k0) + c8);                         \
        }                                                                     \
        asm volatile("cp.async.commit_group;" ::: "memory");                  \
    } while (0)

    ISSUE_STAGE(0, 0);

    const int NK = KQK / BKH;   // 4
    for (int c = 0; c < NK; ++c) {
        if (c + 1 < NK) {
            ISSUE_STAGE((c + 1) & 1, (c + 1) * BKH);
            asm volatile("cp.async.wait_group 1;" ::: "memory");
        } else {
            asm volatile("cp.async.wait_group 0;" ::: "memory");
        }
        __syncthreads();

        // Interleaved zero-fill: 1/NK of this CTA's G/A tiles per chunk,
        // streaming stores drained under the MMA burst below.
#pragma unroll
        for (int l = 0; l < 16 / 4; ++l) {
            int f = tid + (c * 4 + l) * 256;   // 0..4095 float4 positions
            int row = f >> 5;                  // 32 float4 per 128-col row
            int c4 = (f & 31) * 4;
            stg_cs_zero16(Gt + (size_t)row * SS + c4);
            stg_cs_zero16(At + (size_t)row * SS + c4);
        }

        const int st = c & 1;
        const uint32_t ab = asb + (uint32_t)(st * BM * LDSH * 2);
        const uint32_t bbs = bsb + (uint32_t)(st * BN * LDSH * 2);

#pragma unroll
        for (int ks = 0; ks < BKH / 16; ++ks) {
            uint32_t a[4][4];
#pragma unroll
            for (int mt = 0; mt < 4; ++mt) {
                uint32_t addr = ab + (uint32_t)((((warp_m * 64 + mt * 16 + (lane & 15)) * LDSH)
                                 + ks * 16 + (lane >> 4) * 8) * 2);
                asm volatile(
                    "ldmatrix.sync.aligned.m8n8.x4.shared.b16 {%0,%1,%2,%3}, [%4];"
                    : "=r"(a[mt][0]), "=r"(a[mt][1]), "=r"(a[mt][2]), "=r"(a[mt][3])
                    : "r"(addr));
            }
            uint32_t bf[4][2];
#pragma unroll
            for (int g = 0; g < 2; ++g) {
                uint32_t addr = bbs + (uint32_t)((((warp_n * 32 + g * 16 + (lane & 15)) * LDSH)
                                 + ks * 16 + (lane >> 4) * 8) * 2);
                uint32_t r0, r1, r2, r3;
                asm volatile(
                    "ldmatrix.sync.aligned.m8n8.x4.shared.b16 {%0,%1,%2,%3}, [%4];"
                    : "=r"(r0), "=r"(r1), "=r"(r2), "=r"(r3)
                    : "r"(addr));
                bf[g * 2][0] = r0; bf[g * 2][1] = r2;
                bf[g * 2 + 1][0] = r1; bf[g * 2 + 1][1] = r3;
            }
#pragma unroll
            for (int mt = 0; mt < 4; ++mt)
#pragma unroll
                for (int nt = 0; nt < 4; ++nt) {
                    asm volatile(
                        "mma.sync.aligned.m16n8k16.row.col.f32.f16.f16.f32 "
                        "{%0,%1,%2,%3}, {%4,%5,%6,%7}, {%8,%9}, {%0,%1,%2,%3};"
                        : "+f"(acc[mt][nt][0]), "+f"(acc[mt][nt][1]),
                          "+f"(acc[mt][nt][2]), "+f"(acc[mt][nt][3])
                        : "r"(a[mt][0]), "r"(a[mt][1]), "r"(a[mt][2]), "r"(a[mt][3]),
                          "r"(bf[nt][0]), "r"(bf[nt][1]));
                }
        }
        __syncthreads();
    }
#undef ISSUE_STAGE

    // ---------------- Candidate-extraction epilogue --------------------
    float (*wmax)[4] = (float(*)[4])smraw;            // [128][4]
    float* tmax = (float*)(smraw + 128 * 4 * 4);      // [128]
    int*   scnt = (int*)(smraw + 128 * 4 * 4 + 512);  // [128]

#pragma unroll
    for (int mt = 0; mt < 4; ++mt) {
#pragma unroll
        for (int h = 0; h < 2; ++h) {
            float rm = -1e30f;
#pragma unroll
            for (int nt = 0; nt < 4; ++nt)
                rm = fmaxf(rm, fmaxf(acc[mt][nt][h * 2], acc[mt][nt][h * 2 + 1]));
            rm = fmaxf(rm, __shfl_xor_sync(0xffffffffu, rm, 1));
            rm = fmaxf(rm, __shfl_xor_sync(0xffffffffu, rm, 2));
            if ((lane & 3) == 0)
                wmax[warp_m * 64 + mt * 16 + h * 8 + (lane >> 2)][warp_n] = rm;
        }
    }
    __syncthreads();
    if (tid < 128) {
        float t = fmaxf(fmaxf(wmax[tid][0], wmax[tid][1]),
                        fmaxf(wmax[tid][2], wmax[tid][3]));
        tmax[tid] = t;
        scnt[tid] = 0;
    }
    __syncthreads();

    // Extract elements > tile_rowmax - 1 - MARGIN (superset under fp16 error)
#pragma unroll
    for (int mt = 0; mt < 4; ++mt) {
#pragma unroll
        for (int nt = 0; nt < 4; ++nt) {
#pragma unroll
            for (int e = 0; e < 4; ++e) {
                int r = warp_m * 64 + mt * 16 + ((e >> 1) ? 8 : 0) + (lane >> 2);
                float val = acc[mt][nt][e];
                if (val > tmax[r] - 1.0f - MARGIN) {
                    int pos = atomicAdd(&scnt[r], 1);
                    if (pos < NSLOT) {
                        size_t grow = (size_t)b * NN + rowBase + r;
                        size_t slot = (grow * NTILE + tileX) * NSLOT + pos;
                        d_cval[slot] = val;
                        d_cidx[slot] = colBase + warp_n * 32 + nt * 8
                                       + 2 * (lane & 3) + (e & 1);
                    }
                }
            }
        }
    }
    __syncthreads();
    if (tid < 128) {
        size_t grow = (size_t)b * NN + rowBase + tid;
        int cc = scnt[tid];
        d_ccnt[grow * NTILE + tileX] = cc < NSLOT ? cc : NSLOT;
    }
}

// ======= Fused exact-rescore + sparsemax + AV-gather + gate scatter ========
// One warp per row. Gate/A zeros were written by qk_hmma; only scatter here.
__global__ void __launch_bounds__(256) sparse_fused(
    const float* __restrict__ Q, const float* __restrict__ Kk,
    float* __restrict__ G, float* __restrict__ A,
    float* __restrict__ Vout, const float* __restrict__ Vals)
{
    __shared__ float cv[8][32];
    __shared__ int   ci[8][32];

    const int tid = threadIdx.x, wid = tid >> 5, lane = tid & 31;
    const int row = blockIdx.x * 8 + wid;       // 0..32767
    const int b = row >> 11;

    // Lanes 0..15 each own one tile's candidate list (approx values)
    int cnt = 0;
    float tv[NSLOT];
    int   tix[NSLOT];
    if (lane < NTILE) {
        cnt = d_ccnt[(size_t)row * NTILE + lane];
        const size_t base = ((size_t)row * NTILE + lane) * NSLOT;
#pragma unroll
        for (int s = 0; s < NSLOT; ++s) {
            if (s < cnt) { tv[s] = d_cval[base + s]; tix[s] = d_cidx[base + s]; }
        }
    }

    // Approx global row max
    float m = -1e30f;
#pragma unroll
    for (int s = 0; s < NSLOT; ++s)
        if (s < cnt) m = fmaxf(m, tv[s]);
#pragma unroll
    for (int o = 16; o > 0; o >>= 1) m = fmaxf(m, __shfl_xor_sync(0xffffffffu, m, o));
    const float thr = m - 1.0f - MARGIN;

    // Compact survivors (approx val > thr) into shared lists
    int base = 0;
#pragma unroll
    for (int s = 0; s < NSLOT; ++s) {
        bool p = (s < cnt) && (tv[s] > thr);
        unsigned msk = __ballot_sync(0xffffffffu, p);
        if (p) {
            int pos = base + __popc(msk & ((1u << lane) - 1u));
            if (pos < 32) { ci[wid][pos] = tix[s]; }
        }
        base += __popc(msk);
    }
    const int mc = base > 32 ? 32 : base;
    __syncwarp();

    // Exact fp32 rescoring of survivors: warp-cooperative dot products
    const float* Qr = Q + (size_t)row * DD;
    float4 q0 = ((const float4*)Qr)[lane * 2];
    float4 q1 = ((const float4*)Qr)[lane * 2 + 1];
    for (int i = 0; i < mc; ++i) {
        const float* Kr = Kk + ((size_t)b * SS + ci[wid][i]) * DD;
        float4 k0 = ((const float4*)Kr)[lane * 2];
        float4 k1 = ((const float4*)Kr)[lane * 2 + 1];
        float p = q0.x * k0.x + q0.y * k0.y + q0.z * k0.z + q0.w * k0.w
                + q1.x * k1.x + q1.y * k1.y + q1.z * k1.z + q1.w * k1.w;
#pragma unroll
        for (int o = 16; o > 0; o >>= 1) p += __shfl_xor_sync(0xffffffffu, p, o);
        cv[wid][i] = p;   // same value in all lanes
    }
    __syncwarp();

    // Sparsemax on exact candidate scores
    float cand = (lane < mc) ? cv[wid][lane] : -1e30f;
    float me = cand;
#pragma unroll
    for (int o = 16; o > 0; o >>= 1) me = fmaxf(me, __shfl_xor_sync(0xffffffffu, me, o));
    float lo = me - 1.0f, hi = me;
    for (int it = 0; it < 20; ++it) {
        float mid = 0.5f * (lo + hi);
        float s = fmaxf(cand - mid, 0.0f);
#pragma unroll
        for (int o = 16; o > 0; o >>= 1) s += __shfl_xor_sync(0xffffffffu, s, o);
        if (s >= 1.0f) lo = mid; else hi = mid;
    }
    float inz = (cand > lo) ? cand : 0.0f;
    float inc = (cand > lo) ? 1.0f : 0.0f;
#pragma unroll
    for (int o = 16; o > 0; o >>= 1) {
        inz += __shfl_xor_sync(0xffffffffu, inz, o);
        inc += __shfl_xor_sync(0xffffffffu, inc, o);
    }
    const float tau = (inz - 1.0f) / inc;
    const float g = fmaxf(cand - tau, 0.0f);

    // V[row,:] = sum_i g_i * Vals[b, s_i, :]
    float4 acc0 = make_float4(0.f, 0.f, 0.f, 0.f);
    float4 acc1 = make_float4(0.f, 0.f, 0.f, 0.f);
    for (int i = 0; i < mc; ++i) {
        float gi = __shfl_sync(0xffffffffu, g, i);
        if (gi > 0.0f) {
            const float4* vr = (const float4*)(Vals + ((size_t)b * SS + ci[wid][i]) * DD + lane * 8);
            float4 p0 = vr[0], p1 = vr[1];
            acc0.x += gi * p0.x; acc0.y += gi * p0.y; acc0.z += gi * p0.z; acc0.w += gi * p0.w;
            acc1.x += gi * p1.x; acc1.y += gi * p1.y; acc1.z += gi * p1.z; acc1.w += gi * p1.w;
        }
    }
    float4* vo = (float4*)(Vout + (size_t)row * DD + lane * 8);
    vo[0] = acc0; vo[1] = acc1;

    // Scatter nonzero gates (zeros pre-written by qk_hmma)
    if (lane < mc && g > 0.0f) {
        int s = ci[wid][lane];
        G[(size_t)row * SS + s] = g;
        A[(size_t)row * SS + s] = g;
    }
}

// ============================== launch =====================================
extern "C" void kernel_launch(void* const* d_in, const int* in_sizes, int n_in,
                              void* d_out, int out_size)
{
    const float* Q  = (const float*)d_in[0];
    const float* K  = (const float*)d_in[1];
    const float* Vv = (const float*)d_in[2];

    float* out  = (float*)d_out;
    float* Vout = out;
    float* Aout = out + (size_t)BB * NN * DD;
    float* Gout = Aout + (size_t)BB * NN * SS;

    const int QK_SMEM = 2 * (BM + BN) * LDSH * 2;     // 73,728 B
    cudaFuncSetAttribute(qk_hmma, cudaFuncAttributeMaxDynamicSharedMemorySize, QK_SMEM);

    // 1) convert Q,K to fp16 (hi only) into static scratch
    convert_kernel<<<(unsigned)((size_t)BB * NN * DD / 4 / 256), 256>>>(Q, K);

    // 2) approx scores via HMMA -> candidate lists; zero-fills G and A tiles
    dim3 g1(SS / BN, NN / BM, BB);
    qk_hmma<<<g1, 256, QK_SMEM>>>(Gout, Aout);

    // 3) exact rescore + sparsemax + AV gather + gate/A scatter
    sparse_fused<<<BB * NN / 8, 256>>>(Q, K, Gout, Aout, Vout, Vv);
}